// round 10
// baseline (speedup 1.0000x reference)
#include <cuda_runtime.h>
#include <cuda_bf16.h>
#include <math.h>

// ---------------- problem constants (fixed by dataset) ----------------
#define MD    768          // memory dim == query dim
#define THD   256          // NUM_HEADS*HEAD_DIM
#define NHEAD 4
#define HDIM  64
#define NSTEP 3
#define JTOT  32           // B*NHEAD = 8*4
#define NPAD  50176        // padded N (N=50000), = 392*128
#define LN_EPS 1e-5f
#define GRIDW 148          // blocks for weight pass
#define NTILES (NPAD/32)   // 1568 weight tiles
#define RB    128          // rows per scores block
#define MCH   64           // m-chunk for scores smem
#define ENT_SMEM (NPAD * 4)  // 200704 B dynamic smem for entmax z cache

// ---------------- device scratch (static, no allocation) ----------------
__device__ float g_mu[NPAD];
__device__ float g_rs[NPAD];
__device__ __align__(16) float g_rsmu[NPAD];
__device__ __align__(16) float g_xi[JTOT * HDIM];          // [j][d]
__device__ __align__(16) float g_ugT[MD * JTOT];           // [m][j]
__device__ float g_Acoef[JTOT];
__device__ float g_Bcoef[JTOT];
__device__ __align__(16) float g_z [(size_t)JTOT * NPAD];  // [j][n]  (entmax)
__device__ __align__(16) float g_zT[(size_t)NPAD * JTOT];  // [n][j]  (wpass)
__device__ float g_taueff[JTOT];
__device__ float g_W1[JTOT];
__device__ float g_Wm[JTOT];
__device__ __align__(16) float g_rpart[(size_t)GRIDW * MD * JTOT]; // [k][j*768+m]
__device__ __align__(16) float g_outvec[8 * 2048];         // [b][hid]

// ---------------- packed f32x2 helpers ----------------
__device__ __forceinline__ unsigned long long dup2(float x) {
    unsigned long long r;
    asm("mov.b64 %0, {%1, %1};" : "=l"(r) : "f"(x));
    return r;
}
__device__ __forceinline__ float2 unpack2(unsigned long long v) {
    float2 r;
    asm("mov.b64 {%0, %1}, %2;" : "=f"(r.x), "=f"(r.y) : "l"(v));
    return r;
}
#define FFMA2(acc, a, b) asm("fma.rn.f32x2 %0, %1, %2, %0;" : "+l"(acc) : "l"(a), "l"(b))

// ---------------- block reductions ----------------
__device__ __forceinline__ float blockReduceSum(float v, float* sbuf) {
    int lane = threadIdx.x & 31, wid = threadIdx.x >> 5;
    #pragma unroll
    for (int o = 16; o; o >>= 1) v += __shfl_down_sync(0xffffffffu, v, o);
    if (lane == 0) sbuf[wid] = v;
    __syncthreads();
    int nw = (blockDim.x + 31) >> 5;
    v = (threadIdx.x < nw) ? sbuf[threadIdx.x] : 0.f;
    if (wid == 0) {
        #pragma unroll
        for (int o = 16; o; o >>= 1) v += __shfl_down_sync(0xffffffffu, v, o);
    }
    if (threadIdx.x == 0) sbuf[0] = v;
    __syncthreads();
    float r = sbuf[0];
    __syncthreads();
    return r;
}
__device__ __forceinline__ float blockReduceMax(float v, float* sbuf) {
    int lane = threadIdx.x & 31, wid = threadIdx.x >> 5;
    #pragma unroll
    for (int o = 16; o; o >>= 1) v = fmaxf(v, __shfl_down_sync(0xffffffffu, v, o));
    if (lane == 0) sbuf[wid] = v;
    __syncthreads();
    int nw = (blockDim.x + 31) >> 5;
    v = (threadIdx.x < nw) ? sbuf[threadIdx.x] : -1e30f;
    if (wid == 0) {
        #pragma unroll
        for (int o = 16; o; o >>= 1) v = fmaxf(v, __shfl_down_sync(0xffffffffu, v, o));
    }
    if (threadIdx.x == 0) sbuf[0] = v;
    __syncthreads();
    float r = sbuf[0];
    __syncthreads();
    return r;
}
// fused two-value sum reduction: halves barrier count vs two blockReduceSum
__device__ __forceinline__ float2 blockReduceSum2(float a, float b, float* s1, float* s2) {
    int lane = threadIdx.x & 31, wid = threadIdx.x >> 5;
    #pragma unroll
    for (int o = 16; o; o >>= 1) {
        a += __shfl_down_sync(0xffffffffu, a, o);
        b += __shfl_down_sync(0xffffffffu, b, o);
    }
    if (lane == 0) { s1[wid] = a; s2[wid] = b; }
    __syncthreads();
    int nw = (blockDim.x + 31) >> 5;
    a = (threadIdx.x < nw) ? s1[threadIdx.x] : 0.f;
    b = (threadIdx.x < nw) ? s2[threadIdx.x] : 0.f;
    if (wid == 0) {
        #pragma unroll
        for (int o = 16; o; o >>= 1) {
            a += __shfl_down_sync(0xffffffffu, a, o);
            b += __shfl_down_sync(0xffffffffu, b, o);
        }
        if (lane == 0) { s1[0] = a; s2[0] = b; }
    }
    __syncthreads();
    float2 r = make_float2(s1[0], s2[0]);
    __syncthreads();
    return r;
}

// ---------------- K1: LN(query) @ Wq^T -> initial xi ----------------
__global__ void k_query(const float* __restrict__ qe, const float* __restrict__ Wq,
                        const float* __restrict__ gq, const float* __restrict__ bq) {
    int b = blockIdx.x;
    __shared__ float nq[MD];
    __shared__ float sbuf[32];
    const float* x = qe + (size_t)b * MD;
    float s = 0.f, ss = 0.f;
    for (int m = threadIdx.x; m < MD; m += 256) {
        float v = x[m]; s += v; ss += v * v;
    }
    s  = blockReduceSum(s, sbuf);
    ss = blockReduceSum(ss, sbuf);
    float mu = s / (float)MD;
    float rs = rsqrtf(ss / (float)MD - mu * mu + LN_EPS);
    for (int m = threadIdx.x; m < MD; m += 256)
        nq[m] = (x[m] - mu) * rs * gq[m] + bq[m];
    __syncthreads();
    int t = threadIdx.x;
    const float4* wq4 = (const float4*)(Wq + (size_t)t * MD);
    const float4* nq4 = (const float4*)nq;
    float acc = 0.f;
    #pragma unroll 4
    for (int k = 0; k < MD / 4; k++) {
        float4 a = nq4[k], w = wq4[k];
        acc += a.x * w.x + a.y * w.y + a.z * w.z + a.w * w.w;
    }
    g_xi[b * THD + t] = acc;
}

// ---------------- K2a: u[j] = Wk^T xi[j]; fold LN gamma + beta + 0.5*beta_h ----------------
__global__ void k_ug(const float* __restrict__ Wk, const float* __restrict__ gm,
                     const float* __restrict__ bm, const float* __restrict__ lb) {
    int j = blockIdx.x;
    int h = j & (NHEAD - 1);
    __shared__ float xs[HDIM];
    __shared__ float sbuf[32];
    if (threadIdx.x < HDIM) xs[threadIdx.x] = g_xi[j * HDIM + threadIdx.x];
    __syncthreads();
    float hb = 0.5f * expf(lb[h]);
    float aacc = 0.f, bacc = 0.f;
    for (int m = threadIdx.x; m < MD; m += 256) {
        float u = 0.f;
        const float* wkp = Wk + (size_t)(h * HDIM) * MD + m;
        #pragma unroll 8
        for (int d = 0; d < HDIM; d++) u += xs[d] * wkp[(size_t)d * MD];
        float ug = hb * gm[m] * u;
        g_ugT[m * JTOT + j] = ug;
        aacc += ug;
        bacc += hb * bm[m] * u;
    }
    aacc = blockReduceSum(aacc, sbuf);
    bacc = blockReduceSum(bacc, sbuf);
    if (threadIdx.x == 0) { g_Acoef[j] = aacc; g_Bcoef[j] = bacc; }
}

// ---------------- K2b: staged-smem score GEMM, register-prefetch pipelined ----------------
template<bool STATS>
__global__ __launch_bounds__(256) void k_scores2(const float* __restrict__ mb, int N) {
    __shared__ float mbS[MCH * RB];                  // [m][row] 32KB, reused as red in epilogue
    __shared__ __align__(16) float ugs[MCH * JTOT];  // [m][j] 8KB
    __shared__ float sA[JTOT], sB[JTOT];
    int tid = threadIdx.x;
    int r = tid & (RB - 1);
    int half = tid >> 7;                 // 0/1
    int n = blockIdx.x * RB + r;
    int nc = min(n, N - 1);
    // fill-role indices (coalesced: 2 threads per row)
    int rf = tid >> 1;
    int part = tid & 1;
    int nf = min(blockIdx.x * RB + rf, N - 1);
    if (tid < JTOT) { sA[tid] = g_Acoef[tid]; sB[tid] = g_Bcoef[tid]; }

    unsigned long long acc[16];
    #pragma unroll
    for (int p = 0; p < 16; p++) acc[p] = 0ull;
    float s = 0.f, ss = 0.f;

    const float* mbrow = mb + (size_t)nf * MD + part * (MCH / 2);
    float4 pmb[8];
    float4 pug[2];
    {   // prefetch chunk 0
        const float4* r4 = (const float4*)(mbrow);
        #pragma unroll
        for (int k = 0; k < 8; k++) pmb[k] = r4[k];
        const float4* u4 = (const float4*)(g_ugT);
        pug[0] = u4[tid];
        pug[1] = u4[tid + 256];
    }

    #pragma unroll 1
    for (int c = 0; c < MD / MCH; c++) {
        __syncthreads();
        {   // store prefetched tile to smem
            #pragma unroll
            for (int k = 0; k < 8; k++) {
                float4 v = pmb[k];
                int m = part * (MCH / 2) + k * 4;
                mbS[(m + 0) * RB + rf] = v.x;
                mbS[(m + 1) * RB + rf] = v.y;
                mbS[(m + 2) * RB + rf] = v.z;
                mbS[(m + 3) * RB + rf] = v.w;
            }
            ((float4*)ugs)[tid]       = pug[0];
            ((float4*)ugs)[tid + 256] = pug[1];
        }
        __syncthreads();
        if (c + 1 < MD / MCH) {   // issue next chunk's loads before compute
            const float4* r4 = (const float4*)(mbrow + (c + 1) * MCH);
            #pragma unroll
            for (int k = 0; k < 8; k++) pmb[k] = r4[k];
            const float4* u4 = (const float4*)(g_ugT + (c + 1) * MCH * JTOT);
            pug[0] = u4[tid];
            pug[1] = u4[tid + 256];
        }
        int m0 = half * (MCH / 2);
        #pragma unroll
        for (int m = 0; m < MCH / 2; m++) {
            float v = mbS[(m0 + m) * RB + r];
            if (STATS) { s += v; ss = fmaf(v, v, ss); }
            unsigned long long dv = dup2(v);
            const ulonglong2* ug = (const ulonglong2*)(ugs + (m0 + m) * JTOT);
            #pragma unroll
            for (int q = 0; q < 8; q++) {
                ulonglong2 u = ug[q];
                FFMA2(acc[2 * q],     dv, u.x);
                FFMA2(acc[2 * q + 1], dv, u.y);
            }
        }
    }
    __syncthreads();
    float* red  = mbS;          // 4096 floats [j][r]
    float* redS = mbS + 4096;   // stats
    if (half == 1) {
        #pragma unroll
        for (int p = 0; p < 16; p++) {
            float2 v = unpack2(acc[p]);
            red[(2 * p) * RB + r]     = v.x;
            red[(2 * p + 1) * RB + r] = v.y;
        }
        if (STATS) { redS[r] = s; redS[RB + r] = ss; }
    }
    __syncthreads();
    float zv[JTOT];
    if (half == 0) {
        float mu, rs;
        if (STATS) {
            float st = s + redS[r], sst = ss + redS[RB + r];
            mu = st * (1.f / 768.f);
            rs = rsqrtf(sst * (1.f / 768.f) - mu * mu + LN_EPS);
            if (n < N) { g_mu[n] = mu; g_rs[n] = rs; g_rsmu[n] = rs * mu; }
        } else {
            mu = g_mu[nc]; rs = g_rs[nc];
        }
        #pragma unroll
        for (int p = 0; p < 16; p++) {
            float2 v = unpack2(acc[p]);
            int j = 2 * p;
            zv[j]     = rs * (v.x + red[j * RB + r]       - mu * sA[j])     + sB[j];
            zv[j + 1] = rs * (v.y + red[(j + 1) * RB + r] - mu * sA[j + 1]) + sB[j + 1];
        }
        if (n >= N) {
            #pragma unroll
            for (int j = 0; j < JTOT; j++) zv[j] = -1e30f;
        }
        // zT: [n][32] contiguous
        float4* zt4 = (float4*)(g_zT + (size_t)n * JTOT);
        #pragma unroll
        for (int p = 0; p < 8; p++)
            zt4[p] = make_float4(zv[4 * p], zv[4 * p + 1], zv[4 * p + 2], zv[4 * p + 3]);
    }
    __syncthreads();
    if (half == 0) {
        #pragma unroll
        for (int j = 0; j < JTOT; j++) red[j * RB + r] = zv[j];
    }
    __syncthreads();
    {   // coalesced write of z[j][n0..n0+127]
        int j = tid >> 3;
        int q = tid & 7;
        const float4* src = (const float4*)(red + j * RB + q * 16);
        float4* dst = (float4*)(g_z + (size_t)j * NPAD + blockIdx.x * RB + q * 16);
        #pragma unroll
        for (int k = 0; k < 4; k++) dst[k] = src[k];
    }
}

// ---------------- K3: entmax1.5 tau — smem-resident z, safeguarded Newton, early exit ----------------
// R4-proven structure: 1 gmem pass in (z -> smem), Newton sweeps on smem,
// 1 mixed final pass. New: fused f/g reduction (half the barriers) and a
// uniform early exit (f,g,t are block-uniform post-reduction; tn==t at the
// converged fixed point). Safeguard stays STRICT (tn < lo || tn > hi) — see
// R7 post-mortem: bisecting at tn==hi repels the converged iterate.
__global__ __launch_bounds__(1024) void k_entmax5() {
    extern __shared__ float zsh[];   // NPAD floats (196KB)
    int j = blockIdx.x;
    const float4* z4 = (const float4*)(g_z + (size_t)j * NPAD);
    float4* zs4 = (float4*)zsh;
    __shared__ float sbuf[32];
    __shared__ float sb2[32];
    int tid = threadIdx.x;

    // pass 1: stream z -> smem, track max
    float m = -1e30f;
    for (int i = tid; i < NPAD / 4; i += 1024) {
        float4 v = z4[i];
        zs4[i] = v;
        m = fmaxf(m, fmaxf(fmaxf(v.x, v.y), fmaxf(v.z, v.w)));
    }
    float zmax = blockReduceMax(m, sbuf);

    float lo = zmax - 1.0f;
    float hi = zmax;
    float t = lo;
    for (int it = 0; it < 24; ++it) {
        float f = 0.f, g = 0.f;
        for (int i = tid; i < NPAD / 4; i += 1024) {
            float4 v = zs4[i];
            float d;
            d = v.x - t; if (d > 0.f) { f = fmaf(d, d, f); g += d; }
            d = v.y - t; if (d > 0.f) { f = fmaf(d, d, f); g += d; }
            d = v.z - t; if (d > 0.f) { f = fmaf(d, d, f); g += d; }
            d = v.w - t; if (d > 0.f) { f = fmaf(d, d, f); g += d; }
        }
        float2 fg = blockReduceSum2(f, g, sbuf, sb2);
        f = fg.x; g = fg.y;
        if (f > 1.0f) lo = t; else hi = t;
        float tn = t + (f - 1.0f) / fmaxf(2.0f * g, 1e-30f);
        if (tn < lo || tn > hi) tn = 0.5f * (lo + hi);
        if (tn == t) break;   // converged fixed point (uniform across block)
        t = tn;
    }

    // final: W1 and Wm = sum w * rs*mu  (z from smem, rsmu from gmem)
    float w1 = 0.f, wm = 0.f;
    const float4* rm4 = (const float4*)g_rsmu;
    for (int i = tid; i < NPAD / 4; i += 1024) {
        float4 v = zs4[i];
        float4 rm = rm4[i];
        float d, w;
        d = v.x - t; if (d > 0.f) { w = d * d; w1 += w; wm = fmaf(w, rm.x, wm); }
        d = v.y - t; if (d > 0.f) { w = d * d; w1 += w; wm = fmaf(w, rm.y, wm); }
        d = v.z - t; if (d > 0.f) { w = d * d; w1 += w; wm = fmaf(w, rm.z, wm); }
        d = v.w - t; if (d > 0.f) { w = d * d; w1 += w; wm = fmaf(w, rm.w, wm); }
    }
    float2 ww = blockReduceSum2(w1, wm, sbuf, sb2);
    if (tid == 0) { g_taueff[j] = t; g_W1[j] = ww.x; g_Wm[j] = ww.y; }
}

// ---------------- K4: r[j,m] = sum_n w'(j,n) * mb[n,m]  (zT-based + mb prefetch) ----------------
__global__ __launch_bounds__(768) void k_wpass2(const float* __restrict__ mb, int N) {
    __shared__ __align__(16) float wbuf[32 * JTOT];  // [np][jj]
    __shared__ float staus[JTOT];
    int tid = threadIdx.x;
    if (tid < JTOT) staus[tid] = g_taueff[tid];
    unsigned long long acc[16];
    #pragma unroll
    for (int p = 0; p < 16; p++) acc[p] = 0ull;
    __syncthreads();

    float pv[4];
    {   // prefetch first group of first tile
        int s0 = blockIdx.x * 32;
        #pragma unroll
        for (int q = 0; q < 4; q++)
            pv[q] = mb[(size_t)min(s0 + q, N - 1) * MD + tid];
    }

    for (int tile = blockIdx.x; tile < NTILES; tile += GRIDW) {
        int s = tile * 32;
        __syncthreads();
        if (tid < 256) {
            float4 zv = ((const float4*)g_zT)[s * 8 + tid];
            int jj = (tid * 4) & 31;
            int np = (tid * 4) >> 5;
            float rsv = g_rs[s + np];   // 0 for padded rows (never used: w=0)
            float4 w;
            float d;
            d = zv.x - staus[jj];     w.x = (d > 0.f) ? d * d * rsv : 0.f;
            d = zv.y - staus[jj + 1]; w.y = (d > 0.f) ? d * d * rsv : 0.f;
            d = zv.z - staus[jj + 2]; w.z = (d > 0.f) ? d * d * rsv : 0.f;
            d = zv.w - staus[jj + 3]; w.w = (d > 0.f) ? d * d * rsv : 0.f;
            ((float4*)wbuf)[tid] = w;
        }
        __syncthreads();
        const ulonglong2* wq = (const ulonglong2*)wbuf;
        #pragma unroll 1
        for (int np = 0; np < 32; np += 4) {
            float cv0 = pv[0], cv1 = pv[1], cv2 = pv[2], cv3 = pv[3];
            // prefetch next group (or next tile's first group)
            if (np < 28) {
                #pragma unroll
                for (int q = 0; q < 4; q++)
                    pv[q] = mb[(size_t)min(s + np + 4 + q, N - 1) * MD + tid];
            } else {
                int nt = tile + GRIDW;
                if (nt < NTILES) {
                    int s2 = nt * 32;
                    #pragma unroll
                    for (int q = 0; q < 4; q++)
                        pv[q] = mb[(size_t)min(s2 + q, N - 1) * MD + tid];
                }
            }
            unsigned long long d0 = dup2(cv0), d1 = dup2(cv1), d2 = dup2(cv2), d3 = dup2(cv3);
            #pragma unroll
            for (int q = 0; q < 8; q++) {
                ulonglong2 u0 = wq[(np + 0) * 8 + q];
                FFMA2(acc[2 * q], d0, u0.x); FFMA2(acc[2 * q + 1], d0, u0.y);
            }
            #pragma unroll
            for (int q = 0; q < 8; q++) {
                ulonglong2 u1 = wq[(np + 1) * 8 + q];
                FFMA2(acc[2 * q], d1, u1.x); FFMA2(acc[2 * q + 1], d1, u1.y);
            }
            #pragma unroll
            for (int q = 0; q < 8; q++) {
                ulonglong2 u2 = wq[(np + 2) * 8 + q];
                FFMA2(acc[2 * q], d2, u2.x); FFMA2(acc[2 * q + 1], d2, u2.y);
            }
            #pragma unroll
            for (int q = 0; q < 8; q++) {
                ulonglong2 u3 = wq[(np + 3) * 8 + q];
                FFMA2(acc[2 * q], d3, u3.x); FFMA2(acc[2 * q + 1], d3, u3.y);
            }
        }
    }
    float* rp = g_rpart + (size_t)blockIdx.x * (MD * JTOT);
    #pragma unroll
    for (int p = 0; p < 16; p++) {
        float2 v = unpack2(acc[p]);
        rp[(size_t)(2 * p) * MD + tid]     = v.x;
        rp[(size_t)(2 * p + 1) * MD + tid] = v.y;
    }
}

// ---------------- K4c: fused split-K reduce + xi update ----------------
// r[j,m] = sum_k rpart[k][j*768+m]; nmr = gm*(r - Wm) + bm*W1; xi = Wv^T nmr
__global__ __launch_bounds__(256) void k_xiup2(const float* __restrict__ Wv,
                                               const float* __restrict__ gm,
                                               const float* __restrict__ bm) {
    int j = blockIdx.x, h = j & (NHEAD - 1);
    __shared__ float nmr[MD];
    __shared__ float part[256];
    float W1 = g_W1[j], Wm = g_Wm[j];
    for (int m = threadIdx.x; m < MD; m += 256) {
        size_t base = (size_t)j * MD + m;
        float s0 = 0.f, s1 = 0.f, s2 = 0.f, s3 = 0.f;
        #pragma unroll 1
        for (int k = 0; k < GRIDW; k += 4) {
            s0 += g_rpart[(size_t)(k + 0) * (MD * JTOT) + base];
            s1 += g_rpart[(size_t)(k + 1) * (MD * JTOT) + base];
            s2 += g_rpart[(size_t)(k + 2) * (MD * JTOT) + base];
            s3 += g_rpart[(size_t)(k + 3) * (MD * JTOT) + base];
        }
        float rv = (s0 + s1) + (s2 + s3);
        nmr[m] = gm[m] * (rv - Wm) + bm[m] * W1;
    }
    __syncthreads();
    int d = threadIdx.x & 63, pid = threadIdx.x >> 6;
    const float* wv = Wv + (size_t)(h * HDIM + d) * MD;
    float acc = 0.f;
    int m0 = pid * (MD / 4);
    #pragma unroll 4
    for (int m = m0; m < m0 + MD / 4; m++) acc += nmr[m] * wv[m];
    part[threadIdx.x] = acc;
    __syncthreads();
    if (threadIdx.x < 64) {
        float v = part[threadIdx.x] + part[64 + threadIdx.x] +
                  part[128 + threadIdx.x] + part[192 + threadIdx.x];
        g_xi[j * HDIM + threadIdx.x] = v;
    }
}

// ---------------- K5: outvec[b,o] = xi_flat[b] . Wo[o] ----------------
__global__ void k_out(const float* __restrict__ Wo, int HID) {
    int idx = blockIdx.x * 256 + threadIdx.x;
    int b = idx / HID;
    int o = idx % HID;
    __shared__ float xs[THD];
    xs[threadIdx.x] = g_xi[b * THD + threadIdx.x];
    __syncthreads();
    const float4* wo4 = (const float4*)(Wo + (size_t)o * THD);
    const float4* xs4 = (const float4*)xs;
    float acc = 0.f;
    #pragma unroll 8
    for (int k = 0; k < THD / 4; k++) {
        float4 a = xs4[k], w = wo4[k];
        acc += a.x * w.x + a.y * w.y + a.z * w.z + a.w * w.w;
    }
    g_outvec[idx] = acc;
}

// ---------------- K6: broadcast over S ----------------
__global__ void k_bcast(float* __restrict__ out, int S, int HID, long total4) {
    long i = (long)blockIdx.x * blockDim.x + threadIdx.x;
    if (i >= total4) return;
    int h4 = HID / 4;
    long per_b = (long)S * h4;
    int b = (int)(i / per_b);
    int c = (int)(i % h4);
    float4 v = ((const float4*)g_outvec)[b * h4 + c];
    ((float4*)out)[i] = v;
}

// ---------------- launcher ----------------
extern "C" void kernel_launch(void* const* d_in, const int* in_sizes, int n_in,
                              void* d_out, int out_size) {
    const float* qe = (const float*)d_in[1];
    const float* mb = (const float*)d_in[2];
    const float* Wq = (const float*)d_in[3];
    const float* Wk = (const float*)d_in[4];
    const float* Wv = (const float*)d_in[5];
    const float* Wo = (const float*)d_in[6];
    const float* lb = (const float*)d_in[7];
    const float* gq = (const float*)d_in[8];
    const float* bq = (const float*)d_in[9];
    const float* gm = (const float*)d_in[10];
    const float* bm = (const float*)d_in[11];
    float* out = (float*)d_out;

    int B   = in_sizes[1] / MD;     // 8
    int N   = in_sizes[2] / MD;     // 50000
    int HID = in_sizes[6] / THD;    // 2048
    long S  = (long)out_size / ((long)B * HID); // 2048

    // opt-in large dynamic smem for the entmax kernel (idempotent, capture-safe)
    cudaFuncSetAttribute(k_entmax5, cudaFuncAttributeMaxDynamicSharedMemorySize, ENT_SMEM);

    k_query<<<B, 256>>>(qe, Wq, gq, bq);

    for (int step = 0; step < NSTEP; step++) {
        k_ug<<<JTOT, 256>>>(Wk, gm, bm, lb);
        if (step == 0) k_scores2<true><<<NPAD / RB, 256>>>(mb, N);
        else           k_scores2<false><<<NPAD / RB, 256>>>(mb, N);
        k_entmax5<<<JTOT, 1024, ENT_SMEM>>>();
        k_wpass2<<<GRIDW, 768>>>(mb, N);
        k_xiup2<<<JTOT, 256>>>(Wv, gm, bm);
    }

    k_out<<<(B * HID) / 256, 256>>>(Wo, HID);
    long total4 = (long)B * S * HID / 4;
    k_bcast<<<(unsigned)((total4 + 255) / 256), 256>>>(out, (int)S, HID, total4);
}

// round 11
// speedup vs baseline: 1.6499x; 1.6499x over previous
#include <cuda_runtime.h>
#include <cuda_bf16.h>
#include <math.h>

// ---------------- problem constants (fixed by dataset) ----------------
#define MD    768          // memory dim == query dim
#define THD   256          // NUM_HEADS*HEAD_DIM
#define NHEAD 4
#define HDIM  64
#define NSTEP 3
#define JTOT  32           // B*NHEAD = 8*4
#define NPAD  50176        // padded N (N=50000), = 392*128
#define LN_EPS 1e-5f
#define GRIDW 148          // blocks for weight pass
#define NTILES (NPAD/32)   // 1568 weight tiles
#define RB    128          // rows per scores block
#define MCH   64           // m-chunk for scores smem
#define ENT_SMEM (NPAD * 4)  // 200704 B dynamic smem for entmax z cache

// ---------------- device scratch (static, no allocation) ----------------
__device__ float g_mu[NPAD];
__device__ float g_rs[NPAD];
__device__ __align__(16) float g_rsmu[NPAD];
__device__ __align__(16) float g_xi[JTOT * HDIM];          // [j][d]
__device__ __align__(16) float g_ugT[MD * JTOT];           // [m][j]
__device__ float g_Acoef[JTOT];
__device__ float g_Bcoef[JTOT];
__device__ __align__(16) float g_z [(size_t)JTOT * NPAD];  // [j][n]  (entmax)
__device__ __align__(16) float g_zT[(size_t)NPAD * JTOT];  // [n][j]  (wpass)
__device__ float g_taueff[JTOT];
__device__ float g_W1[JTOT];
__device__ float g_Wm[JTOT];
__device__ __align__(16) float g_rpart[(size_t)GRIDW * MD * JTOT]; // [k][j*768+m]
__device__ __align__(16) float g_r[MD * JTOT];             // [j*768+m]
__device__ __align__(16) float g_outvec[8 * 2048];         // [b][hid]

// ---------------- packed f32x2 helpers ----------------
__device__ __forceinline__ unsigned long long dup2(float x) {
    unsigned long long r;
    asm("mov.b64 %0, {%1, %1};" : "=l"(r) : "f"(x));
    return r;
}
__device__ __forceinline__ float2 unpack2(unsigned long long v) {
    float2 r;
    asm("mov.b64 {%0, %1}, %2;" : "=f"(r.x), "=f"(r.y) : "l"(v));
    return r;
}
#define FFMA2(acc, a, b) asm("fma.rn.f32x2 %0, %1, %2, %0;" : "+l"(acc) : "l"(a), "l"(b))

// ---------------- block reductions ----------------
__device__ __forceinline__ float blockReduceSum(float v, float* sbuf) {
    int lane = threadIdx.x & 31, wid = threadIdx.x >> 5;
    #pragma unroll
    for (int o = 16; o; o >>= 1) v += __shfl_down_sync(0xffffffffu, v, o);
    if (lane == 0) sbuf[wid] = v;
    __syncthreads();
    int nw = (blockDim.x + 31) >> 5;
    v = (threadIdx.x < nw) ? sbuf[threadIdx.x] : 0.f;
    if (wid == 0) {
        #pragma unroll
        for (int o = 16; o; o >>= 1) v += __shfl_down_sync(0xffffffffu, v, o);
    }
    if (threadIdx.x == 0) sbuf[0] = v;
    __syncthreads();
    float r = sbuf[0];
    __syncthreads();
    return r;
}
__device__ __forceinline__ float blockReduceMax(float v, float* sbuf) {
    int lane = threadIdx.x & 31, wid = threadIdx.x >> 5;
    #pragma unroll
    for (int o = 16; o; o >>= 1) v = fmaxf(v, __shfl_down_sync(0xffffffffu, v, o));
    if (lane == 0) sbuf[wid] = v;
    __syncthreads();
    int nw = (blockDim.x + 31) >> 5;
    v = (threadIdx.x < nw) ? sbuf[threadIdx.x] : -1e30f;
    if (wid == 0) {
        #pragma unroll
        for (int o = 16; o; o >>= 1) v = fmaxf(v, __shfl_down_sync(0xffffffffu, v, o));
    }
    if (threadIdx.x == 0) sbuf[0] = v;
    __syncthreads();
    float r = sbuf[0];
    __syncthreads();
    return r;
}
// fused two-value sum reduction: halves barrier count vs two blockReduceSum
__device__ __forceinline__ float2 blockReduceSum2(float a, float b, float* s1, float* s2) {
    int lane = threadIdx.x & 31, wid = threadIdx.x >> 5;
    #pragma unroll
    for (int o = 16; o; o >>= 1) {
        a += __shfl_down_sync(0xffffffffu, a, o);
        b += __shfl_down_sync(0xffffffffu, b, o);
    }
    if (lane == 0) { s1[wid] = a; s2[wid] = b; }
    __syncthreads();
    int nw = (blockDim.x + 31) >> 5;
    a = (threadIdx.x < nw) ? s1[threadIdx.x] : 0.f;
    b = (threadIdx.x < nw) ? s2[threadIdx.x] : 0.f;
    if (wid == 0) {
        #pragma unroll
        for (int o = 16; o; o >>= 1) {
            a += __shfl_down_sync(0xffffffffu, a, o);
            b += __shfl_down_sync(0xffffffffu, b, o);
        }
        if (lane == 0) { s1[0] = a; s2[0] = b; }
    }
    __syncthreads();
    float2 r = make_float2(s1[0], s2[0]);
    __syncthreads();
    return r;
}

// ---------------- K1: LN(query) @ Wq^T -> initial xi ----------------
__global__ void k_query(const float* __restrict__ qe, const float* __restrict__ Wq,
                        const float* __restrict__ gq, const float* __restrict__ bq) {
    int b = blockIdx.x;
    __shared__ float nq[MD];
    __shared__ float sbuf[32];
    const float* x = qe + (size_t)b * MD;
    float s = 0.f, ss = 0.f;
    for (int m = threadIdx.x; m < MD; m += 256) {
        float v = x[m]; s += v; ss += v * v;
    }
    s  = blockReduceSum(s, sbuf);
    ss = blockReduceSum(ss, sbuf);
    float mu = s / (float)MD;
    float rs = rsqrtf(ss / (float)MD - mu * mu + LN_EPS);
    for (int m = threadIdx.x; m < MD; m += 256)
        nq[m] = (x[m] - mu) * rs * gq[m] + bq[m];
    __syncthreads();
    int t = threadIdx.x;
    const float4* wq4 = (const float4*)(Wq + (size_t)t * MD);
    const float4* nq4 = (const float4*)nq;
    float acc = 0.f;
    #pragma unroll 4
    for (int k = 0; k < MD / 4; k++) {
        float4 a = nq4[k], w = wq4[k];
        acc += a.x * w.x + a.y * w.y + a.z * w.z + a.w * w.w;
    }
    g_xi[b * THD + t] = acc;
}

// ---------------- K2a: u[j] = Wk^T xi[j]; fold LN gamma + beta + 0.5*beta_h ----------------
__global__ void k_ug(const float* __restrict__ Wk, const float* __restrict__ gm,
                     const float* __restrict__ bm, const float* __restrict__ lb) {
    int j = blockIdx.x;
    int h = j & (NHEAD - 1);
    __shared__ float xs[HDIM];
    __shared__ float sbuf[32];
    if (threadIdx.x < HDIM) xs[threadIdx.x] = g_xi[j * HDIM + threadIdx.x];
    __syncthreads();
    float hb = 0.5f * expf(lb[h]);
    float aacc = 0.f, bacc = 0.f;
    for (int m = threadIdx.x; m < MD; m += 256) {
        float u = 0.f;
        const float* wkp = Wk + (size_t)(h * HDIM) * MD + m;
        #pragma unroll 8
        for (int d = 0; d < HDIM; d++) u += xs[d] * wkp[(size_t)d * MD];
        float ug = hb * gm[m] * u;
        g_ugT[m * JTOT + j] = ug;
        aacc += ug;
        bacc += hb * bm[m] * u;
    }
    aacc = blockReduceSum(aacc, sbuf);
    bacc = blockReduceSum(bacc, sbuf);
    if (threadIdx.x == 0) { g_Acoef[j] = aacc; g_Bcoef[j] = bacc; }
}

// ---------------- K2b: staged-smem score GEMM, register-prefetch pipelined ----------------
template<bool STATS>
__global__ __launch_bounds__(256) void k_scores2(const float* __restrict__ mb, int N) {
    __shared__ float mbS[MCH * RB];                  // [m][row] 32KB, reused as red in epilogue
    __shared__ __align__(16) float ugs[MCH * JTOT];  // [m][j] 8KB
    __shared__ float sA[JTOT], sB[JTOT];
    int tid = threadIdx.x;
    int r = tid & (RB - 1);
    int half = tid >> 7;                 // 0/1
    int n = blockIdx.x * RB + r;
    int nc = min(n, N - 1);
    // fill-role indices (coalesced: 2 threads per row)
    int rf = tid >> 1;
    int part = tid & 1;
    int nf = min(blockIdx.x * RB + rf, N - 1);
    if (tid < JTOT) { sA[tid] = g_Acoef[tid]; sB[tid] = g_Bcoef[tid]; }

    unsigned long long acc[16];
    #pragma unroll
    for (int p = 0; p < 16; p++) acc[p] = 0ull;
    float s = 0.f, ss = 0.f;

    const float* mbrow = mb + (size_t)nf * MD + part * (MCH / 2);
    float4 pmb[8];
    float4 pug[2];
    {   // prefetch chunk 0
        const float4* r4 = (const float4*)(mbrow);
        #pragma unroll
        for (int k = 0; k < 8; k++) pmb[k] = r4[k];
        const float4* u4 = (const float4*)(g_ugT);
        pug[0] = u4[tid];
        pug[1] = u4[tid + 256];
    }

    #pragma unroll 1
    for (int c = 0; c < MD / MCH; c++) {
        __syncthreads();
        {   // store prefetched tile to smem
            #pragma unroll
            for (int k = 0; k < 8; k++) {
                float4 v = pmb[k];
                int m = part * (MCH / 2) + k * 4;
                mbS[(m + 0) * RB + rf] = v.x;
                mbS[(m + 1) * RB + rf] = v.y;
                mbS[(m + 2) * RB + rf] = v.z;
                mbS[(m + 3) * RB + rf] = v.w;
            }
            ((float4*)ugs)[tid]       = pug[0];
            ((float4*)ugs)[tid + 256] = pug[1];
        }
        __syncthreads();
        if (c + 1 < MD / MCH) {   // issue next chunk's loads before compute
            const float4* r4 = (const float4*)(mbrow + (c + 1) * MCH);
            #pragma unroll
            for (int k = 0; k < 8; k++) pmb[k] = r4[k];
            const float4* u4 = (const float4*)(g_ugT + (c + 1) * MCH * JTOT);
            pug[0] = u4[tid];
            pug[1] = u4[tid + 256];
        }
        int m0 = half * (MCH / 2);
        #pragma unroll
        for (int m = 0; m < MCH / 2; m++) {
            float v = mbS[(m0 + m) * RB + r];
            if (STATS) { s += v; ss = fmaf(v, v, ss); }
            unsigned long long dv = dup2(v);
            const ulonglong2* ug = (const ulonglong2*)(ugs + (m0 + m) * JTOT);
            #pragma unroll
            for (int q = 0; q < 8; q++) {
                ulonglong2 u = ug[q];
                FFMA2(acc[2 * q],     dv, u.x);
                FFMA2(acc[2 * q + 1], dv, u.y);
            }
        }
    }
    __syncthreads();
    float* red  = mbS;          // 4096 floats [j][r]
    float* redS = mbS + 4096;   // stats
    if (half == 1) {
        #pragma unroll
        for (int p = 0; p < 16; p++) {
            float2 v = unpack2(acc[p]);
            red[(2 * p) * RB + r]     = v.x;
            red[(2 * p + 1) * RB + r] = v.y;
        }
        if (STATS) { redS[r] = s; redS[RB + r] = ss; }
    }
    __syncthreads();
    float zv[JTOT];
    if (half == 0) {
        float mu, rs;
        if (STATS) {
            float st = s + redS[r], sst = ss + redS[RB + r];
            mu = st * (1.f / 768.f);
            rs = rsqrtf(sst * (1.f / 768.f) - mu * mu + LN_EPS);
            if (n < N) { g_mu[n] = mu; g_rs[n] = rs; g_rsmu[n] = rs * mu; }
        } else {
            mu = g_mu[nc]; rs = g_rs[nc];
        }
        #pragma unroll
        for (int p = 0; p < 16; p++) {
            float2 v = unpack2(acc[p]);
            int j = 2 * p;
            zv[j]     = rs * (v.x + red[j * RB + r]       - mu * sA[j])     + sB[j];
            zv[j + 1] = rs * (v.y + red[(j + 1) * RB + r] - mu * sA[j + 1]) + sB[j + 1];
        }
        if (n >= N) {
            #pragma unroll
            for (int j = 0; j < JTOT; j++) zv[j] = -1e30f;
        }
        // zT: [n][32] contiguous
        float4* zt4 = (float4*)(g_zT + (size_t)n * JTOT);
        #pragma unroll
        for (int p = 0; p < 8; p++)
            zt4[p] = make_float4(zv[4 * p], zv[4 * p + 1], zv[4 * p + 2], zv[4 * p + 3]);
    }
    __syncthreads();
    if (half == 0) {
        #pragma unroll
        for (int j = 0; j < JTOT; j++) red[j * RB + r] = zv[j];
    }
    __syncthreads();
    {   // coalesced write of z[j][n0..n0+127]
        int j = tid >> 3;
        int q = tid & 7;
        const float4* src = (const float4*)(red + j * RB + q * 16);
        float4* dst = (float4*)(g_z + (size_t)j * NPAD + blockIdx.x * RB + q * 16);
        #pragma unroll
        for (int k = 0; k < 4; k++) dst[k] = src[k];
    }
}

// ---------------- K3: entmax1.5 tau — smem-resident z, safeguarded Newton ----------------
// R4-proven structure: 1 gmem pass in (z -> smem), 18 Newton sweeps on smem,
// 1 mixed final pass. Fused f/g reduction halves barrier count. Safeguard is
// STRICT (tn < lo || tn > hi): bisecting at tn==hi repels the converged
// iterate (R7 post-mortem). No early-exit break (R10 post-mortem: exact-float
// equality almost never fires; extra cap iterations are pure cost).
__global__ __launch_bounds__(1024) void k_entmax6() {
    extern __shared__ float zsh[];   // NPAD floats (196KB)
    int j = blockIdx.x;
    const float4* z4 = (const float4*)(g_z + (size_t)j * NPAD);
    float4* zs4 = (float4*)zsh;
    __shared__ float sbuf[32];
    __shared__ float sb2[32];
    int tid = threadIdx.x;

    // pass 1: stream z -> smem, track max
    float m = -1e30f;
    for (int i = tid; i < NPAD / 4; i += 1024) {
        float4 v = z4[i];
        zs4[i] = v;
        m = fmaxf(m, fmaxf(fmaxf(v.x, v.y), fmaxf(v.z, v.w)));
    }
    float zmax = blockReduceMax(m, sbuf);

    float lo = zmax - 1.0f;
    float hi = zmax;
    float t = lo;
    for (int it = 0; it < 18; ++it) {
        float f = 0.f, g = 0.f;
        for (int i = tid; i < NPAD / 4; i += 1024) {
            float4 v = zs4[i];
            float d;
            d = v.x - t; if (d > 0.f) { f = fmaf(d, d, f); g += d; }
            d = v.y - t; if (d > 0.f) { f = fmaf(d, d, f); g += d; }
            d = v.z - t; if (d > 0.f) { f = fmaf(d, d, f); g += d; }
            d = v.w - t; if (d > 0.f) { f = fmaf(d, d, f); g += d; }
        }
        float2 fg = blockReduceSum2(f, g, sbuf, sb2);
        f = fg.x; g = fg.y;
        if (f > 1.0f) lo = t; else hi = t;
        float tn = t + (f - 1.0f) / fmaxf(2.0f * g, 1e-30f);
        if (tn < lo || tn > hi) tn = 0.5f * (lo + hi);
        t = tn;
    }

    // final: W1 and Wm = sum w * rs*mu  (z from smem, rsmu from gmem)
    float w1 = 0.f, wm = 0.f;
    const float4* rm4 = (const float4*)g_rsmu;
    for (int i = tid; i < NPAD / 4; i += 1024) {
        float4 v = zs4[i];
        float4 rm = rm4[i];
        float d, w;
        d = v.x - t; if (d > 0.f) { w = d * d; w1 += w; wm = fmaf(w, rm.x, wm); }
        d = v.y - t; if (d > 0.f) { w = d * d; w1 += w; wm = fmaf(w, rm.y, wm); }
        d = v.z - t; if (d > 0.f) { w = d * d; w1 += w; wm = fmaf(w, rm.z, wm); }
        d = v.w - t; if (d > 0.f) { w = d * d; w1 += w; wm = fmaf(w, rm.w, wm); }
    }
    float2 ww = blockReduceSum2(w1, wm, sbuf, sb2);
    if (tid == 0) { g_taueff[j] = t; g_W1[j] = ww.x; g_Wm[j] = ww.y; }
}

// ---------------- K4: r[j,m] = sum_n w'(j,n) * mb[n,m]  (zT-based + mb prefetch) ----------------
__global__ __launch_bounds__(768) void k_wpass2(const float* __restrict__ mb, int N) {
    __shared__ __align__(16) float wbuf[32 * JTOT];  // [np][jj]
    __shared__ float staus[JTOT];
    int tid = threadIdx.x;
    if (tid < JTOT) staus[tid] = g_taueff[tid];
    unsigned long long acc[16];
    #pragma unroll
    for (int p = 0; p < 16; p++) acc[p] = 0ull;
    __syncthreads();

    float pv[4];
    {   // prefetch first group of first tile
        int s0 = blockIdx.x * 32;
        #pragma unroll
        for (int q = 0; q < 4; q++)
            pv[q] = mb[(size_t)min(s0 + q, N - 1) * MD + tid];
    }

    for (int tile = blockIdx.x; tile < NTILES; tile += GRIDW) {
        int s = tile * 32;
        __syncthreads();
        if (tid < 256) {
            float4 zv = ((const float4*)g_zT)[s * 8 + tid];
            int jj = (tid * 4) & 31;
            int np = (tid * 4) >> 5;
            float rsv = g_rs[s + np];   // 0 for padded rows (never used: w=0)
            float4 w;
            float d;
            d = zv.x - staus[jj];     w.x = (d > 0.f) ? d * d * rsv : 0.f;
            d = zv.y - staus[jj + 1]; w.y = (d > 0.f) ? d * d * rsv : 0.f;
            d = zv.z - staus[jj + 2]; w.z = (d > 0.f) ? d * d * rsv : 0.f;
            d = zv.w - staus[jj + 3]; w.w = (d > 0.f) ? d * d * rsv : 0.f;
            ((float4*)wbuf)[tid] = w;
        }
        __syncthreads();
        const ulonglong2* wq = (const ulonglong2*)wbuf;
        #pragma unroll 1
        for (int np = 0; np < 32; np += 4) {
            float cv0 = pv[0], cv1 = pv[1], cv2 = pv[2], cv3 = pv[3];
            // prefetch next group (or next tile's first group)
            if (np < 28) {
                #pragma unroll
                for (int q = 0; q < 4; q++)
                    pv[q] = mb[(size_t)min(s + np + 4 + q, N - 1) * MD + tid];
            } else {
                int nt = tile + GRIDW;
                if (nt < NTILES) {
                    int s2 = nt * 32;
                    #pragma unroll
                    for (int q = 0; q < 4; q++)
                        pv[q] = mb[(size_t)min(s2 + q, N - 1) * MD + tid];
                }
            }
            unsigned long long d0 = dup2(cv0), d1 = dup2(cv1), d2 = dup2(cv2), d3 = dup2(cv3);
            #pragma unroll
            for (int q = 0; q < 8; q++) {
                ulonglong2 u0 = wq[(np + 0) * 8 + q];
                FFMA2(acc[2 * q], d0, u0.x); FFMA2(acc[2 * q + 1], d0, u0.y);
            }
            #pragma unroll
            for (int q = 0; q < 8; q++) {
                ulonglong2 u1 = wq[(np + 1) * 8 + q];
                FFMA2(acc[2 * q], d1, u1.x); FFMA2(acc[2 * q + 1], d1, u1.y);
            }
            #pragma unroll
            for (int q = 0; q < 8; q++) {
                ulonglong2 u2 = wq[(np + 2) * 8 + q];
                FFMA2(acc[2 * q], d2, u2.x); FFMA2(acc[2 * q + 1], d2, u2.y);
            }
            #pragma unroll
            for (int q = 0; q < 8; q++) {
                ulonglong2 u3 = wq[(np + 3) * 8 + q];
                FFMA2(acc[2 * q], d3, u3.x); FFMA2(acc[2 * q + 1], d3, u3.y);
            }
        }
    }
    float* rp = g_rpart + (size_t)blockIdx.x * (MD * JTOT);
    #pragma unroll
    for (int p = 0; p < 16; p++) {
        float2 v = unpack2(acc[p]);
        rp[(size_t)(2 * p) * MD + tid]     = v.x;
        rp[(size_t)(2 * p + 1) * MD + tid] = v.y;
    }
}

// ---------------- K4b: reduce split-K partials (wide-parallel; R10 fusion regressed) ----------------
__global__ void k_rreduce() {
    int i = blockIdx.x * 128 + threadIdx.x; // i < MD*JTOT = 24576
    float s0 = 0.f, s1 = 0.f, s2 = 0.f, s3 = 0.f;
    #pragma unroll 1
    for (int k = 0; k < GRIDW; k += 4) {
        s0 += g_rpart[(size_t)(k + 0) * (MD * JTOT) + i];
        s1 += g_rpart[(size_t)(k + 1) * (MD * JTOT) + i];
        s2 += g_rpart[(size_t)(k + 2) * (MD * JTOT) + i];
        s3 += g_rpart[(size_t)(k + 3) * (MD * JTOT) + i];
    }
    g_r[i] = (s0 + s1) + (s2 + s3);
}

// ---------------- K4c: xi[j] = Wv^T * (gamma*(r - Wm) + beta*W1) ----------------
__global__ void k_xiup(const float* __restrict__ Wv, const float* __restrict__ gm,
                       const float* __restrict__ bm) {
    int j = blockIdx.x, h = j & (NHEAD - 1);
    __shared__ float nmr[MD];
    __shared__ float part[256];
    float W1 = g_W1[j], Wm = g_Wm[j];
    for (int m = threadIdx.x; m < MD; m += 256)
        nmr[m] = gm[m] * (g_r[j * MD + m] - Wm) + bm[m] * W1;
    __syncthreads();
    int d = threadIdx.x & 63, pid = threadIdx.x >> 6;
    const float* wv = Wv + (size_t)(h * HDIM + d) * MD;
    float acc = 0.f;
    int m0 = pid * (MD / 4);
    #pragma unroll 4
    for (int m = m0; m < m0 + MD / 4; m++) acc += nmr[m] * wv[m];
    part[threadIdx.x] = acc;
    __syncthreads();
    if (threadIdx.x < 64) {
        float v = part[threadIdx.x] + part[64 + threadIdx.x] +
                  part[128 + threadIdx.x] + part[192 + threadIdx.x];
        g_xi[j * HDIM + threadIdx.x] = v;
    }
}

// ---------------- K5: outvec[b,o] = xi_flat[b] . Wo[o] ----------------
__global__ void k_out(const float* __restrict__ Wo, int HID) {
    int idx = blockIdx.x * 256 + threadIdx.x;
    int b = idx / HID;
    int o = idx % HID;
    __shared__ float xs[THD];
    xs[threadIdx.x] = g_xi[b * THD + threadIdx.x];
    __syncthreads();
    const float4* wo4 = (const float4*)(Wo + (size_t)o * THD);
    const float4* xs4 = (const float4*)xs;
    float acc = 0.f;
    #pragma unroll 8
    for (int k = 0; k < THD / 4; k++) {
        float4 a = xs4[k], w = wo4[k];
        acc += a.x * w.x + a.y * w.y + a.z * w.z + a.w * w.w;
    }
    g_outvec[idx] = acc;
}

// ---------------- K6: broadcast over S ----------------
__global__ void k_bcast(float* __restrict__ out, int S, int HID, long total4) {
    long i = (long)blockIdx.x * blockDim.x + threadIdx.x;
    if (i >= total4) return;
    int h4 = HID / 4;
    long per_b = (long)S * h4;
    int b = (int)(i / per_b);
    int c = (int)(i % h4);
    float4 v = ((const float4*)g_outvec)[b * h4 + c];
    ((float4*)out)[i] = v;
}

// ---------------- launcher ----------------
extern "C" void kernel_launch(void* const* d_in, const int* in_sizes, int n_in,
                              void* d_out, int out_size) {
    const float* qe = (const float*)d_in[1];
    const float* mb = (const float*)d_in[2];
    const float* Wq = (const float*)d_in[3];
    const float* Wk = (const float*)d_in[4];
    const float* Wv = (const float*)d_in[5];
    const float* Wo = (const float*)d_in[6];
    const float* lb = (const float*)d_in[7];
    const float* gq = (const float*)d_in[8];
    const float* bq = (const float*)d_in[9];
    const float* gm = (const float*)d_in[10];
    const float* bm = (const float*)d_in[11];
    float* out = (float*)d_out;

    int B   = in_sizes[1] / MD;     // 8
    int N   = in_sizes[2] / MD;     // 50000
    int HID = in_sizes[6] / THD;    // 2048
    long S  = (long)out_size / ((long)B * HID); // 2048

    // opt-in large dynamic smem for the entmax kernel (idempotent, capture-safe)
    cudaFuncSetAttribute(k_entmax6, cudaFuncAttributeMaxDynamicSharedMemorySize, ENT_SMEM);

    k_query<<<B, 256>>>(qe, Wq, gq, bq);

    for (int step = 0; step < NSTEP; step++) {
        k_ug<<<JTOT, 256>>>(Wk, gm, bm, lb);
        if (step == 0) k_scores2<true><<<NPAD / RB, 256>>>(mb, N);
        else           k_scores2<false><<<NPAD / RB, 256>>>(mb, N);
        k_entmax6<<<JTOT, 1024, ENT_SMEM>>>();
        k_wpass2<<<GRIDW, 768>>>(mb, N);
        k_rreduce<<<(MD * JTOT) / 128, 128>>>();
        k_xiup<<<JTOT, 256>>>(Wv, gm, bm);
    }

    k_out<<<(B * HID) / 256, 256>>>(Wo, HID);
    long total4 = (long)B * S * HID / 4;
    k_bcast<<<(unsigned)((total4 + 255) / 256), 256>>>(out, (int)S, HID, total4);
}